// round 15
// baseline (speedup 1.0000x reference)
#include <cuda_runtime.h>
#include <cuda_fp16.h>
#include <math.h>
#include <stdint.h>

// ---------------- problem constants ----------------
#define NNZ   240000
#define CIN   256
#define CCH   128
#define KGRP  12
#define MT    128
#define NRB1  (NNZ / MT)          // 1875
#define NTHR  512

#define AS1   528                 // A smem row stride bytes (K=256 fp16 + 16B pad)
#define AS2   272                 // K=128 fp16 + 16B pad

// smem layout k_mma1 (bytes)
#define SM1_BP    (128 * AS1)
#define SM1_BIAS  (SM1_BP + KGRP * CCH * 4)
#define SM1_TOTAL (SM1_BIAS + 768 * 4)      // 76800
// smem layout k_mma2
#define SM2_B     (128 * AS2)
#define SM2_TOTAL (SM2_B + KGRP * CCH * 4)  // 40960

// ---------------- device scratch ----------------
__device__ __align__(16) uint32_t g_Wfh[6 * 16 * 16 * 64];   // big-GEMM B frags hi (fp16)
__device__ __align__(16) uint32_t g_Wfl[6 * 16 * 16 * 64];   // lo residual (unused in mainloops now)
__device__ __align__(16) uint32_t g_W2h[2 * 8 * 16 * 64];    // out-GEMM B frags hi
__device__ __align__(16) uint32_t g_W2l[2 * 8 * 16 * 64];    // (kept for fallback)
__device__ float g_bcat[768];                                // pair-interleaved bias
__device__ float g_a[(size_t)NNZ * CCH];
__device__ float g_gate[(size_t)NNZ * CIN];
__device__ float g_Bpart[(size_t)NRB1 * KGRP * CCH];
__device__ float g_B2[25 * KGRP * CCH];
__device__ float g_B[KGRP * CCH];

// fast sigmoid: MUFU.EX2 + MUFU.RCP path (~1e-6 rel err, invisible at 5e-4)
__device__ __forceinline__ float sigf(float x) {
    return __fdividef(1.0f, 1.0f + __expf(-x));
}

__device__ __forceinline__ uint32_t smem_u32(const void* p) {
    uint32_t a;
    asm("{ .reg .u64 t; cvta.to.shared.u64 t, %1; cvt.u32.u64 %0, t; }" : "=r"(a) : "l"(p));
    return a;
}
__device__ __forceinline__ void ldm_x4(uint32_t* r, uint32_t addr) {
    asm volatile("ldmatrix.sync.aligned.m8n8.x4.shared.b16 {%0,%1,%2,%3}, [%4];"
        : "=r"(r[0]), "=r"(r[1]), "=r"(r[2]), "=r"(r[3]) : "r"(addr));
}
__device__ __forceinline__ void mma_f16(float* d, const uint32_t* a, uint32_t b0, uint32_t b1) {
    asm volatile("mma.sync.aligned.m16n8k16.row.col.f32.f16.f16.f32 "
        "{%0,%1,%2,%3}, {%4,%5,%6,%7}, {%8,%9}, {%0,%1,%2,%3};"
        : "+f"(d[0]), "+f"(d[1]), "+f"(d[2]), "+f"(d[3])
        : "r"(a[0]), "r"(a[1]), "r"(a[2]), "r"(a[3]), "r"(b0), "r"(b1));
}
__device__ __forceinline__ uint32_t pk(float a, float b) {
    __half2 h = __floats2half2_rn(a, b);
    return *(uint32_t*)&h;
}
__device__ __forceinline__ float fph(float x) {
    return __half2float(__float2half_rn(x));
}

// ---------------- paired mainloop: two 128x16 warp tiles share A fragments, 1-pass ----------------
template<int NKB, int ASTRIDE>
__device__ __forceinline__ void gemm_pair(float acc[2][4][2][4],
                                          uint32_t abase,
                                          const uint2* __restrict__ B0,
                                          const uint2* __restrict__ B1) {
    uint2 b[3][2][2];     // [buf][tile][nb]
    #pragma unroll
    for (int pf = 0; pf < 2; ++pf)
        #pragma unroll
        for (int nb = 0; nb < 2; ++nb) {
            b[pf][0][nb] = B0[(pf * 16 + nb) * 32];
            b[pf][1][nb] = B1[(pf * 16 + nb) * 32];
        }
    #pragma unroll
    for (int kb = 0; kb < NKB; ++kb) {
        const int cur = kb % 3;
        if (kb < NKB - 2) {
            const int dst = (kb + 2) % 3;
            #pragma unroll
            for (int nb = 0; nb < 2; ++nb) {
                b[dst][0][nb] = B0[((kb + 2) * 16 + nb) * 32];
                b[dst][1][nb] = B1[((kb + 2) * 16 + nb) * 32];
            }
        }
        #pragma unroll
        for (int mb = 0; mb < 4; ++mb) {
            uint32_t ah[4];
            ldm_x4(ah, abase + mb * 16 * ASTRIDE + kb * 32);
            #pragma unroll
            for (int t = 0; t < 2; ++t)
                #pragma unroll
                for (int nb = 0; nb < 2; ++nb)
                    mma_f16(acc[t][mb][nb], ah, b[cur][t][nb].x, b[cur][t][nb].y);
        }
    }
}

// ---------------- kernel: pack weights into fragment-ordered fp16 hi/lo ----------------
__global__ void k_pack(const float* __restrict__ Wga, const float* __restrict__ bga,
                       const float* __restrict__ Wla, const float* __restrict__ bla,
                       const float* __restrict__ Wgb, const float* __restrict__ bgb,
                       const float* __restrict__ Wlb, const float* __restrict__ blb,
                       const float* __restrict__ Wgo, const float* __restrict__ bgo,
                       const float* __restrict__ Wlo) {
    int idx = blockIdx.x * blockDim.x + threadIdx.x;
    if (idx < 98304) {
        int lane2 = idx & 63, lane = lane2 >> 1, reg = lane2 & 1;
        int nb = (idx >> 6) & 15, kb = (idx >> 10) & 15, nt = idx >> 14;
        int k0 = kb * 16 + (lane & 3) * 2 + reg * 8;
        int p  = nt * 128 + nb * 8 + (lane >> 2);
        const float* W; int c;
        if (p < 256)      { c = p >> 1;                W = (p & 1) ? Wla : Wga; }
        else if (p < 512) { int q = p - 256; c = q >> 1; W = (q & 1) ? Wlb : Wgb; }
        else              { c = p - 512;               W = Wgo; }
        float w0 = W[c * CIN + k0], w1 = W[c * CIN + k0 + 1];
        float h0 = fph(w0), h1 = fph(w1);
        g_Wfh[idx] = pk(h0, h1);
        g_Wfl[idx] = pk(w0 - h0, w1 - h1);
    } else if (idx < 98304 + 16384) {
        int i2 = idx - 98304;
        int lane2 = i2 & 63, lane = lane2 >> 1, reg = lane2 & 1;
        int nb = (i2 >> 6) & 15, kb = (i2 >> 10) & 7, nt = i2 >> 13;
        int k0 = kb * 16 + (lane & 3) * 2 + reg * 8;
        int j  = nt * 128 + nb * 8 + (lane >> 2);
        float w0 = Wlo[j * CCH + k0], w1 = Wlo[j * CCH + k0 + 1];
        float h0 = fph(w0), h1 = fph(w1);
        g_W2h[i2] = pk(h0, h1);
        g_W2l[i2] = pk(w0 - h0, w1 - h1);
    } else if (idx < 98304 + 16384 + 768) {
        int p = idx - 98304 - 16384;
        float b;
        if (p < 256)      b = (p & 1) ? bla[p >> 1] : bga[p >> 1];
        else if (p < 512) { int q = p - 256; b = (q & 1) ? blb[q >> 1] : bgb[q >> 1]; }
        else              b = bgo[p - 512];
        g_bcat[p] = b;
    }
}

// ---------------- kernel 1: LN + big GEMM (768 cols, 3 tile-pairs) + fused epilogues ----------------
__global__ void __launch_bounds__(NTHR, 1)
k_mma1(const float* __restrict__ vals,
       const float* __restrict__ lng, const float* __restrict__ lnb) {
    extern __shared__ char sm[];
    char*  Ash   = sm;
    float* sBp   = (float*)(sm + SM1_BP);
    float* sbias = (float*)(sm + SM1_BIAS);

    const int tid  = threadIdx.x;
    const int lane = tid & 31;
    const int wid  = tid >> 5;
    const int wm   = wid >> 3;    // 0..1
    const int wn   = wid & 7;     // 0..7
    const size_t row0 = (size_t)blockIdx.x * MT;

    for (int i = tid; i < KGRP * CCH; i += NTHR) sBp[i] = 0.0f;
    for (int i = tid; i < 768; i += NTHR) sbias[i] = g_bcat[i];

    // ---- LN phase: 8 rows per warp, fp16 into smem A image ----
    {
        float4 g0 = *(const float4*)(lng + lane * 4);
        float4 g1 = *(const float4*)(lng + 128 + lane * 4);
        float4 b0 = *(const float4*)(lnb + lane * 4);
        float4 b1 = *(const float4*)(lnb + 128 + lane * 4);
        for (int rr = 0; rr < 8; ++rr) {
            int r = wid * 8 + rr;
            const float* vr = vals + (row0 + r) * CIN;
            float4 v0 = *(const float4*)(vr + lane * 4);
            float4 v1 = *(const float4*)(vr + 128 + lane * 4);
            float s = v0.x + v0.y + v0.z + v0.w + v1.x + v1.y + v1.z + v1.w;
            float q = v0.x*v0.x + v0.y*v0.y + v0.z*v0.z + v0.w*v0.w
                    + v1.x*v1.x + v1.y*v1.y + v1.z*v1.z + v1.w*v1.w;
            #pragma unroll
            for (int o = 16; o; o >>= 1) {
                s += __shfl_xor_sync(0xffffffffu, s, o);
                q += __shfl_xor_sync(0xffffffffu, q, o);
            }
            float mu  = s * (1.0f / 256.0f);
            float var = fmaxf(q * (1.0f / 256.0f) - mu * mu, 0.0f);
            float rs  = rsqrtf(var + 1e-5f);
            float x[8];
            x[0]=(v0.x-mu)*rs*g0.x+b0.x; x[1]=(v0.y-mu)*rs*g0.y+b0.y;
            x[2]=(v0.z-mu)*rs*g0.z+b0.z; x[3]=(v0.w-mu)*rs*g0.w+b0.w;
            x[4]=(v1.x-mu)*rs*g1.x+b1.x; x[5]=(v1.y-mu)*rs*g1.y+b1.y;
            x[6]=(v1.z-mu)*rs*g1.z+b1.z; x[7]=(v1.w-mu)*rs*g1.w+b1.w;
            *(uint2*)(Ash + r*AS1 + lane*8)       = make_uint2(pk(x[0],x[1]), pk(x[2],x[3]));
            *(uint2*)(Ash + r*AS1 + 256 + lane*8) = make_uint2(pk(x[4],x[5]), pk(x[6],x[7]));
        }
    }
    __syncthreads();

    const uint32_t ash = smem_u32(Ash);
    const int lrow = (lane & 7) + ((lane >> 3) & 1) * 8;
    const int lkof = ((lane >> 4) & 1) * 16;
    const uint32_t abase = ash + (uint32_t)((wm * 64 + lrow) * AS1 + lkof);
    const int cls0 = (int)(row0 % KGRP);

    #pragma unroll 1
    for (int np = 0; np < 3; ++np) {      // pair (nt = 2np, 2np+1); np: 0=a, 1=b, 2=gate
        float acc[2][4][2][4];
        #pragma unroll
        for (int t = 0; t < 2; ++t)
            #pragma unroll
            for (int mb = 0; mb < 4; ++mb)
                #pragma unroll
                for (int nb = 0; nb < 2; ++nb)
                    #pragma unroll
                    for (int e = 0; e < 4; ++e) acc[t][mb][nb][e] = 0.0f;

        const uint2* __restrict__ B0 = ((const uint2*)g_Wfh) + ((size_t)((2*np    )*16)*16 + wn*2)*32 + lane;
        const uint2* __restrict__ B1 = ((const uint2*)g_Wfh) + ((size_t)((2*np + 1)*16)*16 + wn*2)*32 + lane;

        gemm_pair<16, AS1>(acc, abase, B0, B1);

        // ---- fused epilogue for the two 128-col tiles of this pair ----
        #pragma unroll
        for (int t = 0; t < 2; ++t) {
            const int nt = 2 * np + t;
            #pragma unroll
            for (int mb = 0; mb < 4; ++mb) {
                #pragma unroll
                for (int nb = 0; nb < 2; ++nb) {
                    int cloc = (wn * 2 + nb) * 8 + (lane & 3) * 2;
                    float bx = sbias[nt * 128 + cloc];
                    float by = sbias[nt * 128 + cloc + 1];
                    int lr0 = wm * 64 + mb * 16 + (lane >> 2);
                    size_t r0 = row0 + lr0, r1 = r0 + 8;
                    float y0 = acc[t][mb][nb][0] + bx;
                    float y1 = acc[t][mb][nb][1] + by;
                    float y2 = acc[t][mb][nb][2] + bx;
                    float y3 = acc[t][mb][nb][3] + by;
                    if (np == 0) {
                        int ch = t * 64 + (cloc >> 1);
                        g_a[r0 * CCH + ch] = sigf(y0) * y1;
                        g_a[r1 * CCH + ch] = sigf(y2) * y3;
                    } else if (np == 1) {
                        int ch = t * 64 + (cloc >> 1);
                        int c0 = (cls0 + lr0) % KGRP;
                        int c1 = (cls0 + lr0 + 8) % KGRP;
                        atomicAdd(&sBp[c0 * CCH + ch], sigf(y0) * y1);
                        atomicAdd(&sBp[c1 * CCH + ch], sigf(y2) * y3);
                    } else {
                        int cg = t * 128 + cloc;
                        *(float2*)(g_gate + r0 * CIN + cg) = make_float2(sigf(y0), sigf(y1));
                        *(float2*)(g_gate + r1 * CIN + cg) = make_float2(sigf(y2), sigf(y3));
                    }
                }
            }
        }
    }
    __syncthreads();
    for (int i = tid; i < KGRP * CCH; i += NTHR)
        g_Bpart[(size_t)blockIdx.x * (KGRP * CCH) + i] = sBp[i];
}

// ---------------- reduce B partials: 2-stage, deterministic ----------------
__global__ void k_redB1() {          // grid (6, 25)
    int d = blockIdx.x * 256 + threadIdx.x;
    int b0 = blockIdx.y * 75;
    float s = 0.0f;
    for (int b = b0; b < b0 + 75; ++b) s += g_Bpart[(size_t)b * (KGRP * CCH) + d];
    g_B2[blockIdx.y * (KGRP * CCH) + d] = s;
}
__global__ void k_redB2() {          // grid 6
    int d = blockIdx.x * 256 + threadIdx.x;
    float s = 0.0f;
    for (int y = 0; y < 25; ++y) s += g_B2[y * (KGRP * CCH) + d];
    g_B[d] = s;
}

// ---------------- kernel 2: tri + LN + out GEMM (256 cols, paired 1-pass) + gate ----------------
__global__ void __launch_bounds__(NTHR, 1)
k_mma2(const float* __restrict__ lnog, const float* __restrict__ lnob,
       const float* __restrict__ blo, float* __restrict__ out) {
    extern __shared__ char sm[];
    char*  Ash = sm;
    float* Bsm = (float*)(sm + SM2_B);

    const int tid  = threadIdx.x;
    const int lane = tid & 31;
    const int wid  = tid >> 5;
    const int wm   = wid >> 3;    // 0..1
    const int wn   = wid & 7;     // 0..7
    const size_t row0 = (size_t)blockIdx.x * MT;

    for (int i = tid; i < KGRP * CCH; i += NTHR) Bsm[i] = g_B[i];
    __syncthreads();

    // ---- tri = a * B[row%12], LN over 128, fp16 into smem ----
    {
        float4 g4 = *(const float4*)(lnog + lane * 4);
        float4 b4 = *(const float4*)(lnob + lane * 4);
        for (int rr = 0; rr < 8; ++rr) {
            int r = wid * 8 + rr;
            size_t gr = row0 + r;
            float4 av = *(const float4*)(g_a + gr * CCH + lane * 4);
            const float* Br = Bsm + (int)(gr % KGRP) * CCH;
            float4 bv = *(const float4*)(Br + lane * 4);
            float t0 = av.x*bv.x, t1 = av.y*bv.y, t2 = av.z*bv.z, t3 = av.w*bv.w;
            float s = t0 + t1 + t2 + t3;
            float q = t0*t0 + t1*t1 + t2*t2 + t3*t3;
            #pragma unroll
            for (int o = 16; o; o >>= 1) {
                s += __shfl_xor_sync(0xffffffffu, s, o);
                q += __shfl_xor_sync(0xffffffffu, q, o);
            }
            float mu  = s * (1.0f / 128.0f);
            float var = fmaxf(q * (1.0f / 128.0f) - mu * mu, 0.0f);
            float rs  = rsqrtf(var + 1e-5f);
            float x0 = (t0 - mu) * rs * g4.x + b4.x;
            float x1 = (t1 - mu) * rs * g4.y + b4.y;
            float x2 = (t2 - mu) * rs * g4.z + b4.z;
            float x3 = (t3 - mu) * rs * g4.w + b4.w;
            *(uint2*)(Ash + r*AS2 + lane*8) = make_uint2(pk(x0,x1), pk(x2,x3));
        }
    }
    __syncthreads();

    const uint32_t ash = smem_u32(Ash);
    const int lrow = (lane & 7) + ((lane >> 3) & 1) * 8;
    const int lkof = ((lane >> 4) & 1) * 16;
    const uint32_t abase = ash + (uint32_t)((wm * 64 + lrow) * AS2 + lkof);

    float acc[2][4][2][4];
    #pragma unroll
    for (int t = 0; t < 2; ++t)
        #pragma unroll
        for (int mb = 0; mb < 4; ++mb)
            #pragma unroll
            for (int nb = 0; nb < 2; ++nb)
                #pragma unroll
                for (int e = 0; e < 4; ++e) acc[t][mb][nb][e] = 0.0f;

    const uint2* __restrict__ B0 = ((const uint2*)g_W2h) + ((size_t)(0*16)  + wn*2)*32 + lane;
    const uint2* __restrict__ B1 = ((const uint2*)g_W2h) + ((size_t)(8*16)  + wn*2)*32 + lane;

    gemm_pair<8, AS2>(acc, abase, B0, B1);   // 1-pass W_lo, both 128-col tiles share A

    // ---- epilogue: out = gate * (acc + blo) for both tiles ----
    #pragma unroll
    for (int t = 0; t < 2; ++t) {
        #pragma unroll
        for (int mb = 0; mb < 4; ++mb) {
            #pragma unroll
            for (int nb = 0; nb < 2; ++nb) {
                int c = t * 128 + (wn * 2 + nb) * 8 + (lane & 3) * 2;
                float2 bias = *(const float2*)(blo + c);
                size_t r0 = row0 + wm * 64 + mb * 16 + (lane >> 2), r1 = r0 + 8;
                float2 gt0 = *(const float2*)(g_gate + r0 * CIN + c);
                float2 gt1 = *(const float2*)(g_gate + r1 * CIN + c);
                *(float2*)(out + r0 * CIN + c) =
                    make_float2(gt0.x * (acc[t][mb][nb][0] + bias.x),
                                gt0.y * (acc[t][mb][nb][1] + bias.y));
                *(float2*)(out + r1 * CIN + c) =
                    make_float2(gt1.x * (acc[t][mb][nb][2] + bias.x),
                                gt1.y * (acc[t][mb][nb][3] + bias.y));
            }
        }
    }
}

// ---------------- launch ----------------
extern "C" void kernel_launch(void* const* d_in, const int* in_sizes, int n_in,
                              void* d_out, int out_size) {
    const float* values  = (const float*)d_in[0];
    const float* ln_in_g = (const float*)d_in[1];
    const float* ln_in_b = (const float*)d_in[2];
    const float* W_ga    = (const float*)d_in[3];
    const float* b_ga    = (const float*)d_in[4];
    const float* W_la    = (const float*)d_in[5];
    const float* b_la    = (const float*)d_in[6];
    const float* W_gb    = (const float*)d_in[7];
    const float* b_gb    = (const float*)d_in[8];
    const float* W_lb    = (const float*)d_in[9];
    const float* b_lb    = (const float*)d_in[10];
    const float* ln_o_g  = (const float*)d_in[11];
    const float* ln_o_b  = (const float*)d_in[12];
    const float* W_go    = (const float*)d_in[13];
    const float* b_go    = (const float*)d_in[14];
    const float* W_lo    = (const float*)d_in[15];
    const float* b_lo    = (const float*)d_in[16];
    float* out = (float*)d_out;

    cudaFuncSetAttribute(k_mma1, cudaFuncAttributeMaxDynamicSharedMemorySize, SM1_TOTAL);
    cudaFuncSetAttribute(k_mma2, cudaFuncAttributeMaxDynamicSharedMemorySize, SM2_TOTAL);

    int pack_threads = 98304 + 16384 + 768;
    k_pack<<<(pack_threads + 255) / 256, 256>>>(W_ga, b_ga, W_la, b_la,
                                                W_gb, b_gb, W_lb, b_lb,
                                                W_go, b_go, W_lo);
    k_mma1<<<NRB1, NTHR, SM1_TOTAL>>>(values, ln_in_g, ln_in_b);
    k_redB1<<<dim3(6, 25), 256>>>();
    k_redB2<<<6, 256>>>();
    k_mma2<<<NRB1, NTHR, SM2_TOTAL>>>(ln_o_g, ln_o_b, b_lo, out);
}

// round 16
// speedup vs baseline: 1.0320x; 1.0320x over previous
#include <cuda_runtime.h>
#include <cuda_fp16.h>
#include <math.h>
#include <stdint.h>

// ---------------- problem constants ----------------
#define NNZ   240000
#define CIN   256
#define CCH   128
#define KGRP  12
#define MT    128
#define NRB1  (NNZ / MT)          // 1875
#define NTHR  512

#define AS1   528                 // A smem row stride bytes (K=256 fp16 + 16B pad)
#define AS2   272                 // K=128 fp16 + 16B pad

// smem layout k_mma1 (bytes)
#define SM1_BP    (128 * AS1)
#define SM1_BIAS  (SM1_BP + KGRP * CCH * 4)
#define SM1_TOTAL (SM1_BIAS + 768 * 4)      // 76800
// smem layout k_mma2
#define SM2_B     (128 * AS2)
#define SM2_TOTAL (SM2_B + KGRP * CCH * 4)  // 40960

// ---------------- device scratch ----------------
__device__ __align__(16) uint32_t g_Wfh[6 * 16 * 16 * 64];   // big-GEMM B frags hi (fp16)
__device__ __align__(16) uint32_t g_Wfl[6 * 16 * 16 * 64];   // lo residual (unused in mainloops)
__device__ __align__(16) uint32_t g_W2h[2 * 8 * 16 * 64];    // out-GEMM B frags hi
__device__ __align__(16) uint32_t g_W2l[2 * 8 * 16 * 64];    // (kept; unused)
__device__ float g_bcat[768];                                // pair-interleaved bias
__device__ float g_a[(size_t)NNZ * CCH];
__device__ float g_gate[(size_t)NNZ * CIN];
__device__ float g_Bpart[(size_t)NRB1 * KGRP * CCH];
__device__ float g_B2[25 * KGRP * CCH];
__device__ float g_B[KGRP * CCH];

// fast sigmoid: MUFU.EX2 + MUFU.RCP path (~1e-6 rel err, invisible at 5e-4)
__device__ __forceinline__ float sigf(float x) {
    return __fdividef(1.0f, 1.0f + __expf(-x));
}

__device__ __forceinline__ uint32_t smem_u32(const void* p) {
    uint32_t a;
    asm("{ .reg .u64 t; cvta.to.shared.u64 t, %1; cvt.u32.u64 %0, t; }" : "=r"(a) : "l"(p));
    return a;
}
__device__ __forceinline__ void ldm_x4(uint32_t* r, uint32_t addr) {
    asm volatile("ldmatrix.sync.aligned.m8n8.x4.shared.b16 {%0,%1,%2,%3}, [%4];"
        : "=r"(r[0]), "=r"(r[1]), "=r"(r[2]), "=r"(r[3]) : "r"(addr));
}
__device__ __forceinline__ void mma_f16(float* d, const uint32_t* a, uint32_t b0, uint32_t b1) {
    asm volatile("mma.sync.aligned.m16n8k16.row.col.f32.f16.f16.f32 "
        "{%0,%1,%2,%3}, {%4,%5,%6,%7}, {%8,%9}, {%0,%1,%2,%3};"
        : "+f"(d[0]), "+f"(d[1]), "+f"(d[2]), "+f"(d[3])
        : "r"(a[0]), "r"(a[1]), "r"(a[2]), "r"(a[3]), "r"(b0), "r"(b1));
}
__device__ __forceinline__ uint32_t pk(float a, float b) {
    __half2 h = __floats2half2_rn(a, b);
    return *(uint32_t*)&h;
}
__device__ __forceinline__ float fph(float x) {
    return __half2float(__float2half_rn(x));
}

// ---------------- paired mainloop (k_mma1): two 128x16 tiles share A, 1-pass ----------------
__device__ __forceinline__ void gemm_pair(float acc[2][4][2][4],
                                          uint32_t abase,
                                          const uint2* __restrict__ B0,
                                          const uint2* __restrict__ B1) {
    uint2 b[3][2][2];     // [buf][tile][nb]
    #pragma unroll
    for (int pf = 0; pf < 2; ++pf)
        #pragma unroll
        for (int nb = 0; nb < 2; ++nb) {
            b[pf][0][nb] = B0[(pf * 16 + nb) * 32];
            b[pf][1][nb] = B1[(pf * 16 + nb) * 32];
        }
    #pragma unroll
    for (int kb = 0; kb < 16; ++kb) {
        const int cur = kb % 3;
        if (kb < 14) {
            const int dst = (kb + 2) % 3;
            #pragma unroll
            for (int nb = 0; nb < 2; ++nb) {
                b[dst][0][nb] = B0[((kb + 2) * 16 + nb) * 32];
                b[dst][1][nb] = B1[((kb + 2) * 16 + nb) * 32];
            }
        }
        #pragma unroll
        for (int mb = 0; mb < 4; ++mb) {
            uint32_t ah[4];
            ldm_x4(ah, abase + mb * 16 * AS1 + kb * 32);
            #pragma unroll
            for (int t = 0; t < 2; ++t)
                #pragma unroll
                for (int nb = 0; nb < 2; ++nb)
                    mma_f16(acc[t][mb][nb], ah, b[cur][t][nb].x, b[cur][t][nb].y);
        }
    }
}

// ---------------- single-tile mainloop (k_mma2): 1-pass, unpaired ----------------
template<int NKB>
__device__ __forceinline__ void gemm_tile1(float acc[4][2][4],
                                           uint32_t abase, int astride,
                                           const uint2* __restrict__ BH) {
    uint2 bh[3][2];
    #pragma unroll
    for (int pf = 0; pf < 2; ++pf)
        #pragma unroll
        for (int nb = 0; nb < 2; ++nb)
            bh[pf][nb] = BH[(pf * 16 + nb) * 32];
    #pragma unroll
    for (int kb = 0; kb < NKB; ++kb) {
        const int cur = kb % 3;
        if (kb < NKB - 2) {
            const int dst = (kb + 2) % 3;
            #pragma unroll
            for (int nb = 0; nb < 2; ++nb)
                bh[dst][nb] = BH[((kb + 2) * 16 + nb) * 32];
        }
        #pragma unroll
        for (int mb = 0; mb < 4; ++mb) {
            uint32_t ah[4];
            ldm_x4(ah, abase + mb * 16 * astride + kb * 32);
            #pragma unroll
            for (int nb = 0; nb < 2; ++nb)
                mma_f16(acc[mb][nb], ah, bh[cur][nb].x, bh[cur][nb].y);
        }
    }
}

// ---------------- kernel: pack weights into fragment-ordered fp16 hi/lo ----------------
__global__ void k_pack(const float* __restrict__ Wga, const float* __restrict__ bga,
                       const float* __restrict__ Wla, const float* __restrict__ bla,
                       const float* __restrict__ Wgb, const float* __restrict__ bgb,
                       const float* __restrict__ Wlb, const float* __restrict__ blb,
                       const float* __restrict__ Wgo, const float* __restrict__ bgo,
                       const float* __restrict__ Wlo) {
    int idx = blockIdx.x * blockDim.x + threadIdx.x;
    if (idx < 98304) {
        int lane2 = idx & 63, lane = lane2 >> 1, reg = lane2 & 1;
        int nb = (idx >> 6) & 15, kb = (idx >> 10) & 15, nt = idx >> 14;
        int k0 = kb * 16 + (lane & 3) * 2 + reg * 8;
        int p  = nt * 128 + nb * 8 + (lane >> 2);
        const float* W; int c;
        if (p < 256)      { c = p >> 1;                W = (p & 1) ? Wla : Wga; }
        else if (p < 512) { int q = p - 256; c = q >> 1; W = (q & 1) ? Wlb : Wgb; }
        else              { c = p - 512;               W = Wgo; }
        float w0 = W[c * CIN + k0], w1 = W[c * CIN + k0 + 1];
        float h0 = fph(w0), h1 = fph(w1);
        g_Wfh[idx] = pk(h0, h1);
        g_Wfl[idx] = pk(w0 - h0, w1 - h1);
    } else if (idx < 98304 + 16384) {
        int i2 = idx - 98304;
        int lane2 = i2 & 63, lane = lane2 >> 1, reg = lane2 & 1;
        int nb = (i2 >> 6) & 15, kb = (i2 >> 10) & 7, nt = i2 >> 13;
        int k0 = kb * 16 + (lane & 3) * 2 + reg * 8;
        int j  = nt * 128 + nb * 8 + (lane >> 2);
        float w0 = Wlo[j * CCH + k0], w1 = Wlo[j * CCH + k0 + 1];
        float h0 = fph(w0), h1 = fph(w1);
        g_W2h[i2] = pk(h0, h1);
        g_W2l[i2] = pk(w0 - h0, w1 - h1);
    } else if (idx < 98304 + 16384 + 768) {
        int p = idx - 98304 - 16384;
        float b;
        if (p < 256)      b = (p & 1) ? bla[p >> 1] : bga[p >> 1];
        else if (p < 512) { int q = p - 256; b = (q & 1) ? blb[q >> 1] : bgb[q >> 1]; }
        else              b = bgo[p - 512];
        g_bcat[p] = b;
    }
}

// ---------------- kernel 1: LN + big GEMM (768 cols, 3 tile-pairs) + fused epilogues ----------------
__global__ void __launch_bounds__(NTHR, 1)
k_mma1(const float* __restrict__ vals,
       const float* __restrict__ lng, const float* __restrict__ lnb) {
    extern __shared__ char sm[];
    char*  Ash   = sm;
    float* sBp   = (float*)(sm + SM1_BP);
    float* sbias = (float*)(sm + SM1_BIAS);

    const int tid  = threadIdx.x;
    const int lane = tid & 31;
    const int wid  = tid >> 5;
    const int wm   = wid >> 3;    // 0..1
    const int wn   = wid & 7;     // 0..7
    const size_t row0 = (size_t)blockIdx.x * MT;

    for (int i = tid; i < KGRP * CCH; i += NTHR) sBp[i] = 0.0f;
    for (int i = tid; i < 768; i += NTHR) sbias[i] = g_bcat[i];

    // ---- LN phase: 8 rows per warp, fp16 into smem A image ----
    {
        float4 g0 = *(const float4*)(lng + lane * 4);
        float4 g1 = *(const float4*)(lng + 128 + lane * 4);
        float4 b0 = *(const float4*)(lnb + lane * 4);
        float4 b1 = *(const float4*)(lnb + 128 + lane * 4);
        for (int rr = 0; rr < 8; ++rr) {
            int r = wid * 8 + rr;
            const float* vr = vals + (row0 + r) * CIN;
            float4 v0 = *(const float4*)(vr + lane * 4);
            float4 v1 = *(const float4*)(vr + 128 + lane * 4);
            float s = v0.x + v0.y + v0.z + v0.w + v1.x + v1.y + v1.z + v1.w;
            float q = v0.x*v0.x + v0.y*v0.y + v0.z*v0.z + v0.w*v0.w
                    + v1.x*v1.x + v1.y*v1.y + v1.z*v1.z + v1.w*v1.w;
            #pragma unroll
            for (int o = 16; o; o >>= 1) {
                s += __shfl_xor_sync(0xffffffffu, s, o);
                q += __shfl_xor_sync(0xffffffffu, q, o);
            }
            float mu  = s * (1.0f / 256.0f);
            float var = fmaxf(q * (1.0f / 256.0f) - mu * mu, 0.0f);
            float rs  = rsqrtf(var + 1e-5f);
            float x[8];
            x[0]=(v0.x-mu)*rs*g0.x+b0.x; x[1]=(v0.y-mu)*rs*g0.y+b0.y;
            x[2]=(v0.z-mu)*rs*g0.z+b0.z; x[3]=(v0.w-mu)*rs*g0.w+b0.w;
            x[4]=(v1.x-mu)*rs*g1.x+b1.x; x[5]=(v1.y-mu)*rs*g1.y+b1.y;
            x[6]=(v1.z-mu)*rs*g1.z+b1.z; x[7]=(v1.w-mu)*rs*g1.w+b1.w;
            *(uint2*)(Ash + r*AS1 + lane*8)       = make_uint2(pk(x[0],x[1]), pk(x[2],x[3]));
            *(uint2*)(Ash + r*AS1 + 256 + lane*8) = make_uint2(pk(x[4],x[5]), pk(x[6],x[7]));
        }
    }
    __syncthreads();

    const uint32_t ash = smem_u32(Ash);
    const int lrow = (lane & 7) + ((lane >> 3) & 1) * 8;
    const int lkof = ((lane >> 4) & 1) * 16;
    const uint32_t abase = ash + (uint32_t)((wm * 64 + lrow) * AS1 + lkof);
    const int cls0 = (int)(row0 % KGRP);

    #pragma unroll 1
    for (int np = 0; np < 3; ++np) {      // pair (nt = 2np, 2np+1); np: 0=a, 1=b, 2=gate
        float acc[2][4][2][4];
        #pragma unroll
        for (int t = 0; t < 2; ++t)
            #pragma unroll
            for (int mb = 0; mb < 4; ++mb)
                #pragma unroll
                for (int nb = 0; nb < 2; ++nb)
                    #pragma unroll
                    for (int e = 0; e < 4; ++e) acc[t][mb][nb][e] = 0.0f;

        const uint2* __restrict__ B0 = ((const uint2*)g_Wfh) + ((size_t)((2*np    )*16)*16 + wn*2)*32 + lane;
        const uint2* __restrict__ B1 = ((const uint2*)g_Wfh) + ((size_t)((2*np + 1)*16)*16 + wn*2)*32 + lane;

        gemm_pair(acc, abase, B0, B1);

        // ---- fused epilogue for the two 128-col tiles of this pair ----
        #pragma unroll
        for (int t = 0; t < 2; ++t) {
            const int nt = 2 * np + t;
            #pragma unroll
            for (int mb = 0; mb < 4; ++mb) {
                #pragma unroll
                for (int nb = 0; nb < 2; ++nb) {
                    int cloc = (wn * 2 + nb) * 8 + (lane & 3) * 2;
                    float bx = sbias[nt * 128 + cloc];
                    float by = sbias[nt * 128 + cloc + 1];
                    int lr0 = wm * 64 + mb * 16 + (lane >> 2);
                    size_t r0 = row0 + lr0, r1 = r0 + 8;
                    float y0 = acc[t][mb][nb][0] + bx;
                    float y1 = acc[t][mb][nb][1] + by;
                    float y2 = acc[t][mb][nb][2] + bx;
                    float y3 = acc[t][mb][nb][3] + by;
                    if (np == 0) {
                        int ch = t * 64 + (cloc >> 1);
                        g_a[r0 * CCH + ch] = sigf(y0) * y1;
                        g_a[r1 * CCH + ch] = sigf(y2) * y3;
                    } else if (np == 1) {
                        int ch = t * 64 + (cloc >> 1);
                        int c0 = (cls0 + lr0) % KGRP;
                        int c1 = (cls0 + lr0 + 8) % KGRP;
                        atomicAdd(&sBp[c0 * CCH + ch], sigf(y0) * y1);
                        atomicAdd(&sBp[c1 * CCH + ch], sigf(y2) * y3);
                    } else {
                        int cg = t * 128 + cloc;
                        *(float2*)(g_gate + r0 * CIN + cg) = make_float2(sigf(y0), sigf(y1));
                        *(float2*)(g_gate + r1 * CIN + cg) = make_float2(sigf(y2), sigf(y3));
                    }
                }
            }
        }
    }
    __syncthreads();
    for (int i = tid; i < KGRP * CCH; i += NTHR)
        g_Bpart[(size_t)blockIdx.x * (KGRP * CCH) + i] = sBp[i];
}

// ---------------- reduce B partials: 2-stage, deterministic ----------------
__global__ void k_redB1() {          // grid (6, 25)
    int d = blockIdx.x * 256 + threadIdx.x;
    int b0 = blockIdx.y * 75;
    float s = 0.0f;
    for (int b = b0; b < b0 + 75; ++b) s += g_Bpart[(size_t)b * (KGRP * CCH) + d];
    g_B2[blockIdx.y * (KGRP * CCH) + d] = s;
}
__global__ void k_redB2() {          // grid 6
    int d = blockIdx.x * 256 + threadIdx.x;
    float s = 0.0f;
    for (int y = 0; y < 25; ++y) s += g_B2[y * (KGRP * CCH) + d];
    g_B[d] = s;
}

// ---------------- kernel 2: tri + LN + out GEMM (256 cols, 1-pass unpaired) + gate ----------------
__global__ void __launch_bounds__(NTHR, 1)
k_mma2(const float* __restrict__ lnog, const float* __restrict__ lnob,
       const float* __restrict__ blo, float* __restrict__ out) {
    extern __shared__ char sm[];
    char*  Ash = sm;
    float* Bsm = (float*)(sm + SM2_B);

    const int tid  = threadIdx.x;
    const int lane = tid & 31;
    const int wid  = tid >> 5;
    const int wm   = wid >> 3;    // 0..1
    const int wn   = wid & 7;     // 0..7
    const size_t row0 = (size_t)blockIdx.x * MT;

    for (int i = tid; i < KGRP * CCH; i += NTHR) Bsm[i] = g_B[i];
    __syncthreads();

    // ---- tri = a * B[row%12], LN over 128, fp16 into smem ----
    {
        float4 g4 = *(const float4*)(lnog + lane * 4);
        float4 b4 = *(const float4*)(lnob + lane * 4);
        for (int rr = 0; rr < 8; ++rr) {
            int r = wid * 8 + rr;
            size_t gr = row0 + r;
            float4 av = *(const float4*)(g_a + gr * CCH + lane * 4);
            const float* Br = Bsm + (int)(gr % KGRP) * CCH;
            float4 bv = *(const float4*)(Br + lane * 4);
            float t0 = av.x*bv.x, t1 = av.y*bv.y, t2 = av.z*bv.z, t3 = av.w*bv.w;
            float s = t0 + t1 + t2 + t3;
            float q = t0*t0 + t1*t1 + t2*t2 + t3*t3;
            #pragma unroll
            for (int o = 16; o; o >>= 1) {
                s += __shfl_xor_sync(0xffffffffu, s, o);
                q += __shfl_xor_sync(0xffffffffu, q, o);
            }
            float mu  = s * (1.0f / 128.0f);
            float var = fmaxf(q * (1.0f / 128.0f) - mu * mu, 0.0f);
            float rs  = rsqrtf(var + 1e-5f);
            float x0 = (t0 - mu) * rs * g4.x + b4.x;
            float x1 = (t1 - mu) * rs * g4.y + b4.y;
            float x2 = (t2 - mu) * rs * g4.z + b4.z;
            float x3 = (t3 - mu) * rs * g4.w + b4.w;
            *(uint2*)(Ash + r*AS2 + lane*8) = make_uint2(pk(x0,x1), pk(x2,x3));
        }
    }
    __syncthreads();

    const uint32_t ash = smem_u32(Ash);
    const int lrow = (lane & 7) + ((lane >> 3) & 1) * 8;
    const int lkof = ((lane >> 4) & 1) * 16;
    const uint32_t abase = ash + (uint32_t)((wm * 64 + lrow) * AS2 + lkof);

    #pragma unroll 1
    for (int nt = 0; nt < 2; ++nt) {
        float acc[4][2][4];
        #pragma unroll
        for (int mb = 0; mb < 4; ++mb)
            #pragma unroll
            for (int nb = 0; nb < 2; ++nb)
                #pragma unroll
                for (int e = 0; e < 4; ++e) acc[mb][nb][e] = 0.0f;

        const uint2* __restrict__ BH = ((const uint2*)g_W2h) + ((size_t)(nt*8)*16 + wn*2)*32 + lane;

        gemm_tile1<8>(acc, abase, AS2, BH);   // 1-pass W_lo

        // ---- epilogue: out = gate * (acc + blo) ----
        #pragma unroll
        for (int mb = 0; mb < 4; ++mb) {
            #pragma unroll
            for (int nb = 0; nb < 2; ++nb) {
                int c = nt * 128 + (wn * 2 + nb) * 8 + (lane & 3) * 2;
                float2 bias = *(const float2*)(blo + c);
                size_t r0 = row0 + wm * 64 + mb * 16 + (lane >> 2), r1 = r0 + 8;
                float2 gt0 = *(const float2*)(g_gate + r0 * CIN + c);
                float2 gt1 = *(const float2*)(g_gate + r1 * CIN + c);
                *(float2*)(out + r0 * CIN + c) =
                    make_float2(gt0.x * (acc[mb][nb][0] + bias.x),
                                gt0.y * (acc[mb][nb][1] + bias.y));
                *(float2*)(out + r1 * CIN + c) =
                    make_float2(gt1.x * (acc[mb][nb][2] + bias.x),
                                gt1.y * (acc[mb][nb][3] + bias.y));
            }
        }
    }
}

// ---------------- launch ----------------
extern "C" void kernel_launch(void* const* d_in, const int* in_sizes, int n_in,
                              void* d_out, int out_size) {
    const float* values  = (const float*)d_in[0];
    const float* ln_in_g = (const float*)d_in[1];
    const float* ln_in_b = (const float*)d_in[2];
    const float* W_ga    = (const float*)d_in[3];
    const float* b_ga    = (const float*)d_in[4];
    const float* W_la    = (const float*)d_in[5];
    const float* b_la    = (const float*)d_in[6];
    const float* W_gb    = (const float*)d_in[7];
    const float* b_gb    = (const float*)d_in[8];
    const float* W_lb    = (const float*)d_in[9];
    const float* b_lb    = (const float*)d_in[10];
    const float* ln_o_g  = (const float*)d_in[11];
    const float* ln_o_b  = (const float*)d_in[12];
    const float* W_go    = (const float*)d_in[13];
    const float* b_go    = (const float*)d_in[14];
    const float* W_lo    = (const float*)d_in[15];
    const float* b_lo    = (const float*)d_in[16];
    float* out = (float*)d_out;

    cudaFuncSetAttribute(k_mma1, cudaFuncAttributeMaxDynamicSharedMemorySize, SM1_TOTAL);
    cudaFuncSetAttribute(k_mma2, cudaFuncAttributeMaxDynamicSharedMemorySize, SM2_TOTAL);

    int pack_threads = 98304 + 16384 + 768;
    k_pack<<<(pack_threads + 255) / 256, 256>>>(W_ga, b_ga, W_la, b_la,
                                                W_gb, b_gb, W_lb, b_lb,
                                                W_go, b_go, W_lo);
    k_mma1<<<NRB1, NTHR, SM1_TOTAL>>>(values, ln_in_g, ln_in_b);
    k_redB1<<<dim3(6, 25), 256>>>();
    k_redB2<<<6, 256>>>();
    k_mma2<<<NRB1, NTHR, SM2_TOTAL>>>(ln_o_g, ln_o_b, b_lo, out);
}